// round 3
// baseline (speedup 1.0000x reference)
#include <cuda_runtime.h>
#include <math.h>

#define QLEN 1024
#define BSZ 4
#define DM 1024
#define NH 16
#define DH 64
#define HD (NH*DH)          /* 1024 */
#define ROWS (QLEN*BSZ)     /* 4096 */

// ---------------- scratch (device globals; no allocation allowed) ----------
__device__ __align__(16) float g_heads[ROWS * 3 * HD];  // [i,b, 3*1024]  ~50 MB
__device__ __align__(16) float g_rk[QLEN * HD];         // [m, n*64+d]     4 MB
__device__ __align__(16) float g_vec[ROWS * HD];        // [i,b, n*64+d]  16 MB
__device__ __align__(16) float g_ao[ROWS * DM];         // attn_out       16 MB

// ---------------- generic SGEMM: C[M,N] = A[M,K] @ B[K,N], row-major -------
// 128x128 tile, BK=8, 256 threads, 8x8 per thread. M,N,K multiples of 128/8.
__global__ __launch_bounds__(256) void sgemm128(
    const float* __restrict__ A, const float* __restrict__ B,
    float* __restrict__ C, int M, int N, int K)
{
    __shared__ float As[8][128];
    __shared__ float Bs[8][128];

    int tid  = threadIdx.x;
    int col0 = blockIdx.x * 128;
    int row0 = blockIdx.y * 128;
    int tx = tid & 15, ty = tid >> 4;

    int arow = tid >> 1;          // 0..127
    int acol = (tid & 1) * 4;     // 0,4
    int brow = tid >> 5;          // 0..7
    int bcol = (tid & 31) * 4;    // 0..124

    float acc[8][8];
#pragma unroll
    for (int m = 0; m < 8; m++)
#pragma unroll
        for (int n = 0; n < 8; n++) acc[m][n] = 0.f;

    for (int k0 = 0; k0 < K; k0 += 8) {
        float4 a4 = *(const float4*)&A[(size_t)(row0 + arow) * K + k0 + acol];
        As[acol + 0][arow] = a4.x;
        As[acol + 1][arow] = a4.y;
        As[acol + 2][arow] = a4.z;
        As[acol + 3][arow] = a4.w;
        float4 b4 = *(const float4*)&B[(size_t)(k0 + brow) * N + col0 + bcol];
        *(float4*)&Bs[brow][bcol] = b4;
        __syncthreads();

#pragma unroll
        for (int k = 0; k < 8; k++) {
            float a[8], b[8];
            *(float4*)&a[0] = *(float4*)&As[k][ty * 8];
            *(float4*)&a[4] = *(float4*)&As[k][ty * 8 + 4];
            *(float4*)&b[0] = *(float4*)&Bs[k][tx * 8];
            *(float4*)&b[4] = *(float4*)&Bs[k][tx * 8 + 4];
#pragma unroll
            for (int m = 0; m < 8; m++)
#pragma unroll
                for (int n = 0; n < 8; n++) acc[m][n] += a[m] * b[n];
        }
        __syncthreads();
    }

#pragma unroll
    for (int m = 0; m < 8; m++) {
        float4 c0 = make_float4(acc[m][0], acc[m][1], acc[m][2], acc[m][3]);
        float4 c1 = make_float4(acc[m][4], acc[m][5], acc[m][6], acc[m][7]);
        size_t off = (size_t)(row0 + ty * 8 + m) * N + col0 + tx * 8;
        *(float4*)&C[off]     = c0;
        *(float4*)&C[off + 4] = c1;
    }
}

// ---------------- fused rel-attention (flash-style online softmax) ---------
// Grid: (QLEN/64, NH, BSZ). Block 256 (16x16), each thread 4x4 micro-tile.
// S[i,j] = (q_i+rwb)·k_j + (q_i+rrb)·r_k[1023-i+j]   (j<=i, else masked)
#define ATTN_SMEM_FLOATS (5*64*65 + 64*129)

__global__ __launch_bounds__(256) void attn_kernel(
    const float* __restrict__ heads, const float* __restrict__ rk,
    const float* __restrict__ rwb, const float* __restrict__ rrb,
    float* __restrict__ vec)
{
    extern __shared__ float smf[];
    float* qwT = smf;                 // [d=64][row 65]
    float* qrT = qwT + 64 * 65;       // [d][row]
    float* ksT = qrT + 64 * 65;       // [d][col]
    float* vs  = ksT + 64 * 65;       // [j][d]
    float* psT = vs  + 64 * 65;       // [j][row]
    float* rkT = psT + 64 * 65;       // [d][band 129]

    int tid = threadIdx.x;
    int i0 = blockIdx.x * 64;
    int n  = blockIdx.y;
    int b  = blockIdx.z;
    int tx = tid & 15, ty = tid >> 4;
    int rbase = ty * 4, cbase = tx * 4;

    // load q tile, add both biases
    for (int idx = tid; idx < 4096; idx += 256) {
        int r = idx >> 6, d = idx & 63;
        float v = heads[(size_t)((i0 + r) * BSZ + b) * 3072 + n * 64 + d];
        qwT[d * 65 + r] = v + rwb[n * 64 + d];
        qrT[d * 65 + r] = v + rrb[n * 64 + d];
    }

    float m_i[4], l_i[4], acc[4][4];
#pragma unroll
    for (int m = 0; m < 4; m++) {
        m_i[m] = -3.0e38f; l_i[m] = 0.f;
#pragma unroll
        for (int d2 = 0; d2 < 4; d2++) acc[m][d2] = 0.f;
    }

    const float scale = 0.125f;  // 1/sqrt(64)
    int ntiles = blockIdx.x + 1; // causal: only jt <= it

    for (int jt = 0; jt < ntiles; ++jt) {
        int j0 = jt * 64;
        __syncthreads();  // protects q-stores (iter 0) and psT/vs reuse

        for (int idx = tid; idx < 4096; idx += 256) {
            int c = idx >> 6, d = idx & 63;
            size_t off = (size_t)((j0 + c) * BSZ + b) * 3072 + n * 64 + d;
            ksT[d * 65 + c] = heads[off + 1024];
            vs[c * 65 + d]  = heads[off + 2048];
        }
        int base = 960 - i0 + j0;  // >= 0 always; top rows may exceed QLEN (masked region)
        for (int idx = tid; idx < 127 * 64; idx += 256) {
            int t = idx >> 6, d = idx & 63;
            int g = base + t;
            rkT[d * 129 + t] = (g < QLEN) ? rk[(size_t)g * HD + n * 64 + d] : 0.f;
        }
        __syncthreads();

        // ---- S = AC + BD
        float s[4][4];
#pragma unroll
        for (int m = 0; m < 4; m++)
#pragma unroll
            for (int c2 = 0; c2 < 4; c2++) s[m][c2] = 0.f;

        for (int d = 0; d < 64; ++d) {
            float aw[4], ar[4], bk[4];
#pragma unroll
            for (int m = 0; m < 4; m++) {
                aw[m] = qwT[d * 65 + rbase + m];
                ar[m] = qrT[d * 65 + rbase + m];
            }
#pragma unroll
            for (int c2 = 0; c2 < 4; c2++) bk[c2] = ksT[d * 65 + cbase + c2];
#pragma unroll
            for (int m = 0; m < 4; m++) {
                int bo = d * 129 + 63 - (rbase + m) + cbase;  // band row = 63 - r + c
#pragma unroll
                for (int c2 = 0; c2 < 4; c2++)
                    s[m][c2] += aw[m] * bk[c2] + ar[m] * rkT[bo + c2];
            }
        }

        // ---- mask + scale + online softmax update
#pragma unroll
        for (int m = 0; m < 4; m++) {
            int i = i0 + rbase + m;
            float rmax = -3.0e38f;
#pragma unroll
            for (int c2 = 0; c2 < 4; c2++) {
                int j = j0 + cbase + c2;
                float v = (j <= i) ? s[m][c2] * scale : -1.0e30f;
                s[m][c2] = v;
                rmax = fmaxf(rmax, v);
            }
#pragma unroll
            for (int o = 1; o < 16; o <<= 1)
                rmax = fmaxf(rmax, __shfl_xor_sync(0xffffffffu, rmax, o));
            float mn = fmaxf(m_i[m], rmax);
            float corr = __expf(m_i[m] - mn);
            m_i[m] = mn;
            float rsum = 0.f;
#pragma unroll
            for (int c2 = 0; c2 < 4; c2++) {
                float p = __expf(s[m][c2] - mn);
                s[m][c2] = p;
                rsum += p;
            }
#pragma unroll
            for (int o = 1; o < 16; o <<= 1)
                rsum += __shfl_xor_sync(0xffffffffu, rsum, o);
            l_i[m] = l_i[m] * corr + rsum;
#pragma unroll
            for (int d2 = 0; d2 < 4; d2++) acc[m][d2] *= corr;
#pragma unroll
            for (int c2 = 0; c2 < 4; c2++)
                psT[(cbase + c2) * 65 + rbase + m] = s[m][c2];
        }
        __syncthreads();

        // ---- acc += P @ V  (thread owns rows rbase.., d-cols cbase..)
        for (int j = 0; j < 64; ++j) {
            float pj[4], vv[4];
#pragma unroll
            for (int m = 0; m < 4; m++) pj[m] = psT[j * 65 + rbase + m];
#pragma unroll
            for (int d2 = 0; d2 < 4; d2++) vv[d2] = vs[j * 65 + cbase + d2];
#pragma unroll
            for (int m = 0; m < 4; m++)
#pragma unroll
                for (int d2 = 0; d2 < 4; d2++) acc[m][d2] += pj[m] * vv[d2];
        }
    }

#pragma unroll
    for (int m = 0; m < 4; m++) {
        float inv = 1.0f / l_i[m];
#pragma unroll
        for (int d2 = 0; d2 < 4; d2++)
            vec[(size_t)((i0 + rbase + m) * BSZ + b) * HD + n * 64 + cbase + d2] =
                acc[m][d2] * inv;
    }
}

// ---------------- residual + LayerNorm -------------------------------------
__global__ __launch_bounds__(256) void ln_kernel(
    const float* __restrict__ w, const float* __restrict__ ao,
    const float* __restrict__ gamma, const float* __restrict__ beta,
    float* __restrict__ out)
{
    int row = blockIdx.x;
    const float* wr = w  + (size_t)row * DM;
    const float* ar = ao + (size_t)row * DM;
    int tid = threadIdx.x;

    float x[4];
    float sum = 0.f, ssq = 0.f;
#pragma unroll
    for (int k = 0; k < 4; k++) {
        int d = tid + k * 256;
        x[k] = wr[d] + ar[d];
        sum += x[k];
        ssq += x[k] * x[k];
    }
#pragma unroll
    for (int o = 16; o > 0; o >>= 1) {
        sum += __shfl_xor_sync(0xffffffffu, sum, o);
        ssq += __shfl_xor_sync(0xffffffffu, ssq, o);
    }
    __shared__ float reds[8], redq[8];
    __shared__ float mu_s, rstd_s;
    int wid = tid >> 5, lane = tid & 31;
    if (lane == 0) { reds[wid] = sum; redq[wid] = ssq; }
    __syncthreads();
    if (tid == 0) {
        float s = 0.f, q = 0.f;
#pragma unroll
        for (int i = 0; i < 8; i++) { s += reds[i]; q += redq[i]; }
        float mu = s * (1.0f / DM);
        float var = q * (1.0f / DM) - mu * mu;
        mu_s = mu;
        rstd_s = rsqrtf(var + 1e-5f);
    }
    __syncthreads();
    float mu = mu_s, rstd = rstd_s;
#pragma unroll
    for (int k = 0; k < 4; k++) {
        int d = tid + k * 256;
        out[(size_t)row * DM + d] = (x[k] - mu) * rstd * gamma[d] + beta[d];
    }
}

// ---------------- launch ----------------------------------------------------
extern "C" void kernel_launch(void* const* d_in, const int* in_sizes, int n_in,
                              void* d_out, int out_size)
{
    const float* w    = (const float*)d_in[0];
    const float* r    = (const float*)d_in[1];
    const float* rwb  = (const float*)d_in[2];
    const float* rrb  = (const float*)d_in[3];
    // d_in[4] = attn_mask: deterministic causal tril -> applied analytically
    const float* Wqkv = (const float*)d_in[5];
    const float* Wr   = (const float*)d_in[6];
    const float* Wo   = (const float*)d_in[7];
    const float* gam  = (const float*)d_in[8];
    const float* bet  = (const float*)d_in[9];
    float* out = (float*)d_out;

    float *heads, *rkp, *vecp, *aop;
    cudaGetSymbolAddress((void**)&heads, g_heads);
    cudaGetSymbolAddress((void**)&rkp,   g_rk);
    cudaGetSymbolAddress((void**)&vecp,  g_vec);
    cudaGetSymbolAddress((void**)&aop,   g_ao);

    // 1) heads = w @ W_qkv   [4096,1024]x[1024,3072]
    sgemm128<<<dim3(3072 / 128, 4096 / 128), 256>>>(w, Wqkv, heads, ROWS, 3 * HD, DM);
    // 2) r_k = r @ W_r       [1024,1024]x[1024,1024]
    sgemm128<<<dim3(HD / 128, QLEN / 128), 256>>>(r, Wr, rkp, QLEN, HD, DM);

    // 3) fused relative attention
    size_t attn_smem = (size_t)ATTN_SMEM_FLOATS * sizeof(float);
    cudaFuncSetAttribute(attn_kernel, cudaFuncAttributeMaxDynamicSharedMemorySize,
                         (int)attn_smem);
    attn_kernel<<<dim3(QLEN / 64, NH, BSZ), 256, attn_smem>>>(heads, rkp, rwb, rrb, vecp);

    // 4) attn_out = vec @ W_o
    sgemm128<<<dim3(DM / 128, ROWS / 128), 256>>>(vecp, Wo, aop, ROWS, DM, HD);

    // 5) residual + layernorm
    ln_kernel<<<ROWS, 256>>>(w, aop, gam, bet, out);
}

// round 5
// speedup vs baseline: 1.2344x; 1.2344x over previous
#include <cuda_runtime.h>
#include <cuda_bf16.h>
#include <math.h>

#define QLEN 1024
#define BSZ 4
#define DM 1024
#define NH 16
#define DH 64
#define HD (NH*DH)          /* 1024 */
#define ROWS (QLEN*BSZ)     /* 4096 */

// ---------------- scratch (device globals; no allocation allowed) ----------
__device__ __align__(16) float g_heads[ROWS * 3 * HD];  // [i,b, 3*1024]
__device__ __align__(16) float g_rk[QLEN * HD];         // [m, n*64+d]
__device__ __align__(16) float g_vec[ROWS * HD];        // [i,b, n*64+d]
__device__ __align__(16) float g_ao[ROWS * DM];         // attn_out

// ============================================================================
// Tensor-core GEMM: C[M,N] = A[M,K] @ B[K,N], fp32 in/out.
// Internally bf16 split (hi+lo), 3 MMAs per product => ~2^-18 per-term error.
// 128x128x32 tile, 256 threads (8 warps), warp-tile 64x32 via m16n8k16.
// Requires M%128==0, N%128==0, K%32==0.
// ============================================================================

__device__ __forceinline__ void mma16816(float* c, const unsigned* a, const unsigned* b)
{
    asm volatile(
        "mma.sync.aligned.m16n8k16.row.col.f32.bf16.bf16.f32 "
        "{%0,%1,%2,%3}, {%4,%5,%6,%7}, {%8,%9}, {%0,%1,%2,%3};\n"
        : "+f"(c[0]), "+f"(c[1]), "+f"(c[2]), "+f"(c[3])
        : "r"(a[0]), "r"(a[1]), "r"(a[2]), "r"(a[3]), "r"(b[0]), "r"(b[1]));
}

#define APAD 40   /* bf16 elems per row (32 data + 8 pad) -> 20 words, conflict-free frags */

__global__ __launch_bounds__(256) void gemm_mma(
    const float* __restrict__ A, const float* __restrict__ B,
    float* __restrict__ C, int M, int N, int K)
{
    __shared__ __nv_bfloat16 Ah[128][APAD];
    __shared__ __nv_bfloat16 Al[128][APAD];
    __shared__ __nv_bfloat16 Bh[128][APAD];   // stored [n][k]
    __shared__ __nv_bfloat16 Bl[128][APAD];

    const int tid  = threadIdx.x;
    const int row0 = blockIdx.y * 128;
    const int col0 = blockIdx.x * 128;
    const int warp = tid >> 5, lane = tid & 31;
    const int wm = warp & 1;        // 0..1  (64 rows each)
    const int wn = warp >> 1;       // 0..3  (32 cols each)
    const int g  = lane >> 2;       // group 0..7
    const int tg = lane & 3;        // thread-in-group

    float acc[4][4][4];
#pragma unroll
    for (int mf = 0; mf < 4; mf++)
#pragma unroll
        for (int nf = 0; nf < 4; nf++)
#pragma unroll
            for (int i = 0; i < 4; i++) acc[mf][nf][i] = 0.f;

    for (int k0 = 0; k0 < K; k0 += 32) {
        __syncthreads();   // previous compute done before refill

        // ---- fill A tile (128x32): 1024 float4, 4 per thread
#pragma unroll
        for (int i = 0; i < 4; i++) {
            int idx = tid + i * 256;
            int r = idx >> 3;           // /8 float4 per row
            int kq = idx & 7;
            float4 v = *(const float4*)&A[(size_t)(row0 + r) * K + k0 + kq * 4];
            __nv_bfloat16 h0 = __float2bfloat16(v.x);
            __nv_bfloat16 h1 = __float2bfloat16(v.y);
            __nv_bfloat16 h2 = __float2bfloat16(v.z);
            __nv_bfloat16 h3 = __float2bfloat16(v.w);
            __nv_bfloat16 l0 = __float2bfloat16(v.x - __bfloat162float(h0));
            __nv_bfloat16 l1 = __float2bfloat16(v.y - __bfloat162float(h1));
            __nv_bfloat16 l2 = __float2bfloat16(v.z - __bfloat162float(h2));
            __nv_bfloat16 l3 = __float2bfloat16(v.w - __bfloat162float(h3));
            unsigned ph0 = ((unsigned)__bfloat16_as_ushort(h1) << 16) | __bfloat16_as_ushort(h0);
            unsigned ph1 = ((unsigned)__bfloat16_as_ushort(h3) << 16) | __bfloat16_as_ushort(h2);
            unsigned pl0 = ((unsigned)__bfloat16_as_ushort(l1) << 16) | __bfloat16_as_ushort(l0);
            unsigned pl1 = ((unsigned)__bfloat16_as_ushort(l3) << 16) | __bfloat16_as_ushort(l2);
            *(unsigned*)&Ah[r][kq * 4]     = ph0;
            *(unsigned*)&Ah[r][kq * 4 + 2] = ph1;
            *(unsigned*)&Al[r][kq * 4]     = pl0;
            *(unsigned*)&Al[r][kq * 4 + 2] = pl1;
        }

        // ---- fill B tile (32k x 128n) transposed into [n][k]
#pragma unroll
        for (int i = 0; i < 16; i++) {
            int e = tid + i * 256;      // 0..4095
            int kk = e >> 7;            // 0..31
            int n  = e & 127;
            float v = B[(size_t)(k0 + kk) * N + col0 + n];
            __nv_bfloat16 h = __float2bfloat16(v);
            Bh[n][kk] = h;
            Bl[n][kk] = __float2bfloat16(v - __bfloat162float(h));
        }
        __syncthreads();

        // ---- compute: 2 k-steps of 16
#pragma unroll
        for (int ks = 0; ks < 2; ks++) {
            int kb = ks * 16 + tg * 2;   // bf16 index of this thread's k-pair

            unsigned bh[4][2], bl[4][2];
#pragma unroll
            for (int nf = 0; nf < 4; nf++) {
                int n = wn * 32 + nf * 8 + g;
                bh[nf][0] = *(unsigned*)&Bh[n][kb];
                bh[nf][1] = *(unsigned*)&Bh[n][kb + 8];
                bl[nf][0] = *(unsigned*)&Bl[n][kb];
                bl[nf][1] = *(unsigned*)&Bl[n][kb + 8];
            }
#pragma unroll
            for (int mf = 0; mf < 4; mf++) {
                int r = wm * 64 + mf * 16 + g;
                unsigned ah[4], al[4];
                ah[0] = *(unsigned*)&Ah[r][kb];
                ah[1] = *(unsigned*)&Ah[r + 8][kb];
                ah[2] = *(unsigned*)&Ah[r][kb + 8];
                ah[3] = *(unsigned*)&Ah[r + 8][kb + 8];
                al[0] = *(unsigned*)&Al[r][kb];
                al[1] = *(unsigned*)&Al[r + 8][kb];
                al[2] = *(unsigned*)&Al[r][kb + 8];
                al[3] = *(unsigned*)&Al[r + 8][kb + 8];
#pragma unroll
                for (int nf = 0; nf < 4; nf++) {
                    mma16816(acc[mf][nf], ah, bh[nf]);   // hi*hi
                    mma16816(acc[mf][nf], ah, bl[nf]);   // hi*lo
                    mma16816(acc[mf][nf], al, bh[nf]);   // lo*hi
                }
            }
        }
    }

    // ---- epilogue
#pragma unroll
    for (int mf = 0; mf < 4; mf++) {
        int r = row0 + wm * 64 + mf * 16 + g;
#pragma unroll
        for (int nf = 0; nf < 4; nf++) {
            int c = col0 + wn * 32 + nf * 8 + tg * 2;
            *(float2*)&C[(size_t)r * N + c]       = make_float2(acc[mf][nf][0], acc[mf][nf][1]);
            *(float2*)&C[(size_t)(r + 8) * N + c] = make_float2(acc[mf][nf][2], acc[mf][nf][3]);
        }
    }
}

// ---------------- fused rel-attention (flash-style online softmax) ---------
// Grid: (QLEN/64, NH, BSZ). Block 256 (16x16), each thread 4x4 micro-tile.
// S[i,j] = (q_i+rwb)·k_j + (q_i+rrb)·r_k[1023-i+j]   (j<=i, else masked)
#define ATTN_SMEM_FLOATS (5*64*65 + 64*129)

__global__ __launch_bounds__(256) void attn_kernel(
    const float* __restrict__ heads, const float* __restrict__ rk,
    const float* __restrict__ rwb, const float* __restrict__ rrb,
    float* __restrict__ vec)
{
    extern __shared__ float smf[];
    float* qwT = smf;                 // [d=64][row 65]
    float* qrT = qwT + 64 * 65;       // [d][row]
    float* ksT = qrT + 64 * 65;       // [d][col]
    float* vs  = ksT + 64 * 65;       // [j][d]
    float* psT = vs  + 64 * 65;       // [j][row]
    float* rkT = psT + 64 * 65;       // [d][band 129]

    int tid = threadIdx.x;
    int i0 = blockIdx.x * 64;
    int n  = blockIdx.y;
    int b  = blockIdx.z;
    int tx = tid & 15, ty = tid >> 4;
    int rbase = ty * 4, cbase = tx * 4;

    // load q tile, add both biases
    for (int idx = tid; idx < 4096; idx += 256) {
        int r = idx >> 6, d = idx & 63;
        float v = heads[(size_t)((i0 + r) * BSZ + b) * 3072 + n * 64 + d];
        qwT[d * 65 + r] = v + rwb[n * 64 + d];
        qrT[d * 65 + r] = v + rrb[n * 64 + d];
    }

    float m_i[4], l_i[4], acc[4][4];
#pragma unroll
    for (int m = 0; m < 4; m++) {
        m_i[m] = -3.0e38f; l_i[m] = 0.f;
#pragma unroll
        for (int d2 = 0; d2 < 4; d2++) acc[m][d2] = 0.f;
    }

    const float scale = 0.125f;  // 1/sqrt(64)
    int ntiles = blockIdx.x + 1; // causal: only jt <= it

    for (int jt = 0; jt < ntiles; ++jt) {
        int j0 = jt * 64;
        __syncthreads();  // protects q-stores (iter 0) and psT/vs reuse

        for (int idx = tid; idx < 4096; idx += 256) {
            int c = idx >> 6, d = idx & 63;
            size_t off = (size_t)((j0 + c) * BSZ + b) * 3072 + n * 64 + d;
            ksT[d * 65 + c] = heads[off + 1024];
            vs[c * 65 + d]  = heads[off + 2048];
        }
        int base = 960 - i0 + j0;  // >= 0 always; top rows may exceed QLEN (masked region)
        for (int idx = tid; idx < 127 * 64; idx += 256) {
            int t = idx >> 6, d = idx & 63;
            int g = base + t;
            rkT[d * 129 + t] = (g < QLEN) ? rk[(size_t)g * HD + n * 64 + d] : 0.f;
        }
        __syncthreads();

        // ---- S = AC + BD
        float s[4][4];
#pragma unroll
        for (int m = 0; m < 4; m++)
#pragma unroll
            for (int c2 = 0; c2 < 4; c2++) s[m][c2] = 0.f;

        for (int d = 0; d < 64; ++d) {
            float aw[4], ar[4], bk[4];
#pragma unroll
            for (int m = 0; m < 4; m++) {
                aw[m] = qwT[d * 65 + rbase + m];
                ar[m] = qrT[d * 65 + rbase + m];
            }
#pragma unroll
            for (int c2 = 0; c2 < 4; c2++) bk[c2] = ksT[d * 65 + cbase + c2];
#pragma unroll
            for (int m = 0; m < 4; m++) {
                int bo = d * 129 + 63 - (rbase + m) + cbase;  // band row = 63 - r + c
#pragma unroll
                for (int c2 = 0; c2 < 4; c2++)
                    s[m][c2] += aw[m] * bk[c2] + ar[m] * rkT[bo + c2];
            }
        }

        // ---- mask + scale + online softmax update
#pragma unroll
        for (int m = 0; m < 4; m++) {
            int i = i0 + rbase + m;
            float rmax = -3.0e38f;
#pragma unroll
            for (int c2 = 0; c2 < 4; c2++) {
                int j = j0 + cbase + c2;
                float v = (j <= i) ? s[m][c2] * scale : -1.0e30f;
                s[m][c2] = v;
                rmax = fmaxf(rmax, v);
            }
#pragma unroll
            for (int o = 1; o < 16; o <<= 1)
                rmax = fmaxf(rmax, __shfl_xor_sync(0xffffffffu, rmax, o));
            float mn = fmaxf(m_i[m], rmax);
            float corr = __expf(m_i[m] - mn);
            m_i[m] = mn;
            float rsum = 0.f;
#pragma unroll
            for (int c2 = 0; c2 < 4; c2++) {
                float p = __expf(s[m][c2] - mn);
                s[m][c2] = p;
                rsum += p;
            }
#pragma unroll
            for (int o = 1; o < 16; o <<= 1)
                rsum += __shfl_xor_sync(0xffffffffu, rsum, o);
            l_i[m] = l_i[m] * corr + rsum;
#pragma unroll
            for (int d2 = 0; d2 < 4; d2++) acc[m][d2] *= corr;
#pragma unroll
            for (int c2 = 0; c2 < 4; c2++)
                psT[(cbase + c2) * 65 + rbase + m] = s[m][c2];
        }
        __syncthreads();

        // ---- acc += P @ V  (thread owns rows rbase.., d-cols cbase..)
        for (int j = 0; j < 64; ++j) {
            float pj[4], vv[4];
#pragma unroll
            for (int m = 0; m < 4; m++) pj[m] = psT[j * 65 + rbase + m];
#pragma unroll
            for (int d2 = 0; d2 < 4; d2++) vv[d2] = vs[j * 65 + cbase + d2];
#pragma unroll
            for (int m = 0; m < 4; m++)
#pragma unroll
                for (int d2 = 0; d2 < 4; d2++) acc[m][d2] += pj[m] * vv[d2];
        }
    }

#pragma unroll
    for (int m = 0; m < 4; m++) {
        float inv = 1.0f / l_i[m];
#pragma unroll
        for (int d2 = 0; d2 < 4; d2++)
            vec[(size_t)((i0 + rbase + m) * BSZ + b) * HD + n * 64 + cbase + d2] =
                acc[m][d2] * inv;
    }
}

// ---------------- residual + LayerNorm -------------------------------------
__global__ __launch_bounds__(256) void ln_kernel(
    const float* __restrict__ w, const float* __restrict__ ao,
    const float* __restrict__ gamma, const float* __restrict__ beta,
    float* __restrict__ out)
{
    int row = blockIdx.x;
    const float* wr = w  + (size_t)row * DM;
    const float* ar = ao + (size_t)row * DM;
    int tid = threadIdx.x;

    float x[4];
    float sum = 0.f, ssq = 0.f;
#pragma unroll
    for (int k = 0; k < 4; k++) {
        int d = tid + k * 256;
        x[k] = wr[d] + ar[d];
        sum += x[k];
        ssq += x[k] * x[k];
    }
#pragma unroll
    for (int o = 16; o > 0; o >>= 1) {
        sum += __shfl_xor_sync(0xffffffffu, sum, o);
        ssq += __shfl_xor_sync(0xffffffffu, ssq, o);
    }
    __shared__ float reds[8], redq[8];
    __shared__ float mu_s, rstd_s;
    int wid = tid >> 5, lane = tid & 31;
    if (lane == 0) { reds[wid] = sum; redq[wid] = ssq; }
    __syncthreads();
    if (tid == 0) {
        float s = 0.f, q = 0.f;
#pragma unroll
        for (int i = 0; i < 8; i++) { s += reds[i]; q += redq[i]; }
        float mu = s * (1.0f / DM);
        float var = q * (1.0f / DM) - mu * mu;
        mu_s = mu;
        rstd_s = rsqrtf(var + 1e-5f);
    }
    __syncthreads();
    float mu = mu_s, rstd = rstd_s;
#pragma unroll
    for (int k = 0; k < 4; k++) {
        int d = tid + k * 256;
        out[(size_t)row * DM + d] = (x[k] - mu) * rstd * gamma[d] + beta[d];
    }
}

// ---------------- launch ----------------------------------------------------
extern "C" void kernel_launch(void* const* d_in, const int* in_sizes, int n_in,
                              void* d_out, int out_size)
{
    const float* w    = (const float*)d_in[0];
    const float* r    = (const float*)d_in[1];
    const float* rwb  = (const float*)d_in[2];
    const float* rrb  = (const float*)d_in[3];
    // d_in[4] = attn_mask: deterministic causal tril -> applied analytically
    const float* Wqkv = (const float*)d_in[5];
    const float* Wr   = (const float*)d_in[6];
    const float* Wo   = (const float*)d_in[7];
    const float* gam  = (const float*)d_in[8];
    const float* bet  = (const float*)d_in[9];
    float* out = (float*)d_out;

    float *heads, *rkp, *vecp, *aop;
    cudaGetSymbolAddress((void**)&heads, g_heads);
    cudaGetSymbolAddress((void**)&rkp,   g_rk);
    cudaGetSymbolAddress((void**)&vecp,  g_vec);
    cudaGetSymbolAddress((void**)&aop,   g_ao);

    // 1) heads = w @ W_qkv   [4096,1024]x[1024,3072]  (tensor cores, bf16-split)
    gemm_mma<<<dim3(3072 / 128, 4096 / 128), 256>>>(w, Wqkv, heads, ROWS, 3 * HD, DM);
    // 2) r_k = r @ W_r       [1024,1024]x[1024,1024]
    gemm_mma<<<dim3(HD / 128, QLEN / 128), 256>>>(r, Wr, rkp, QLEN, HD, DM);

    // 3) fused relative attention
    size_t attn_smem = (size_t)ATTN_SMEM_FLOATS * sizeof(float);
    cudaFuncSetAttribute(attn_kernel, cudaFuncAttributeMaxDynamicSharedMemorySize,
                         (int)attn_smem);
    attn_kernel<<<dim3(QLEN / 64, NH, BSZ), 256, attn_smem>>>(heads, rkp, rwb, rrb, vecp);

    // 4) attn_out = vec @ W_o
    gemm_mma<<<dim3(DM / 128, ROWS / 128), 256>>>(vecp, Wo, aop, ROWS, DM, HD);

    // 5) residual + layernorm
    ln_kernel<<<ROWS, 256>>>(w, aop, gam, bet, out);
}

// round 6
// speedup vs baseline: 1.8454x; 1.4950x over previous
#include <cuda_runtime.h>
#include <cuda_bf16.h>
#include <math.h>

#define QLEN 1024
#define BSZ 4
#define DM 1024
#define NH 16
#define DH 64
#define HD (NH*DH)          /* 1024 */
#define ROWS (QLEN*BSZ)     /* 4096 */

// ---------------- scratch (device globals; no allocation allowed) ----------
__device__ __align__(16) float g_heads[ROWS * 3 * HD];  // [i,b, 3*1024]
__device__ __align__(16) float g_rk[QLEN * HD];         // [m, n*64+d]
__device__ __align__(16) float g_vec[ROWS * HD];        // [i,b, n*64+d]
__device__ __align__(16) float g_ao[ROWS * DM];         // attn_out

// ============================================================================
// m16n8k16 bf16 MMA with fp32 accumulate
// ============================================================================
__device__ __forceinline__ void mma16816(float* c, const unsigned* a, const unsigned* b)
{
    asm volatile(
        "mma.sync.aligned.m16n8k16.row.col.f32.bf16.bf16.f32 "
        "{%0,%1,%2,%3}, {%4,%5,%6,%7}, {%8,%9}, {%0,%1,%2,%3};\n"
        : "+f"(c[0]), "+f"(c[1]), "+f"(c[2]), "+f"(c[3])
        : "r"(a[0]), "r"(a[1]), "r"(a[2]), "r"(a[3]), "r"(b[0]), "r"(b[1]));
}

__device__ __forceinline__ unsigned pack_bf2(__nv_bfloat16 a, __nv_bfloat16 b)
{
    return ((unsigned)__bfloat16_as_ushort(b) << 16) | __bfloat16_as_ushort(a);
}

// ============================================================================
// Tensor-core GEMM: C[M,N] = A[M,K] @ B[K,N], fp32 in/out (bf16 hi/lo split).
// ============================================================================
#define APAD 40

__global__ __launch_bounds__(256) void gemm_mma(
    const float* __restrict__ A, const float* __restrict__ B,
    float* __restrict__ C, int M, int N, int K)
{
    __shared__ __nv_bfloat16 Ah[128][APAD];
    __shared__ __nv_bfloat16 Al[128][APAD];
    __shared__ __nv_bfloat16 Bh[128][APAD];   // stored [n][k]
    __shared__ __nv_bfloat16 Bl[128][APAD];

    const int tid  = threadIdx.x;
    const int row0 = blockIdx.y * 128;
    const int col0 = blockIdx.x * 128;
    const int warp = tid >> 5, lane = tid & 31;
    const int wm = warp & 1;
    const int wn = warp >> 1;
    const int g  = lane >> 2;
    const int tg = lane & 3;

    float acc[4][4][4];
#pragma unroll
    for (int mf = 0; mf < 4; mf++)
#pragma unroll
        for (int nf = 0; nf < 4; nf++)
#pragma unroll
            for (int i = 0; i < 4; i++) acc[mf][nf][i] = 0.f;

    for (int k0 = 0; k0 < K; k0 += 32) {
        __syncthreads();

#pragma unroll
        for (int i = 0; i < 4; i++) {
            int idx = tid + i * 256;
            int r = idx >> 3;
            int kq = idx & 7;
            float4 v = *(const float4*)&A[(size_t)(row0 + r) * K + k0 + kq * 4];
            __nv_bfloat16 h0 = __float2bfloat16(v.x);
            __nv_bfloat16 h1 = __float2bfloat16(v.y);
            __nv_bfloat16 h2 = __float2bfloat16(v.z);
            __nv_bfloat16 h3 = __float2bfloat16(v.w);
            __nv_bfloat16 l0 = __float2bfloat16(v.x - __bfloat162float(h0));
            __nv_bfloat16 l1 = __float2bfloat16(v.y - __bfloat162float(h1));
            __nv_bfloat16 l2 = __float2bfloat16(v.z - __bfloat162float(h2));
            __nv_bfloat16 l3 = __float2bfloat16(v.w - __bfloat162float(h3));
            *(unsigned*)&Ah[r][kq * 4]     = pack_bf2(h0, h1);
            *(unsigned*)&Ah[r][kq * 4 + 2] = pack_bf2(h2, h3);
            *(unsigned*)&Al[r][kq * 4]     = pack_bf2(l0, l1);
            *(unsigned*)&Al[r][kq * 4 + 2] = pack_bf2(l2, l3);
        }

#pragma unroll
        for (int i = 0; i < 16; i++) {
            int e = tid + i * 256;
            int kk = e >> 7;
            int n  = e & 127;
            float v = B[(size_t)(k0 + kk) * N + col0 + n];
            __nv_bfloat16 h = __float2bfloat16(v);
            Bh[n][kk] = h;
            Bl[n][kk] = __float2bfloat16(v - __bfloat162float(h));
        }
        __syncthreads();

#pragma unroll
        for (int ks = 0; ks < 2; ks++) {
            int kb = ks * 16 + tg * 2;

            unsigned bh[4][2], bl[4][2];
#pragma unroll
            for (int nf = 0; nf < 4; nf++) {
                int n = wn * 32 + nf * 8 + g;
                bh[nf][0] = *(unsigned*)&Bh[n][kb];
                bh[nf][1] = *(unsigned*)&Bh[n][kb + 8];
                bl[nf][0] = *(unsigned*)&Bl[n][kb];
                bl[nf][1] = *(unsigned*)&Bl[n][kb + 8];
            }
#pragma unroll
            for (int mf = 0; mf < 4; mf++) {
                int r = wm * 64 + mf * 16 + g;
                unsigned ah[4], al[4];
                ah[0] = *(unsigned*)&Ah[r][kb];
                ah[1] = *(unsigned*)&Ah[r + 8][kb];
                ah[2] = *(unsigned*)&Ah[r][kb + 8];
                ah[3] = *(unsigned*)&Ah[r + 8][kb + 8];
                al[0] = *(unsigned*)&Al[r][kb];
                al[1] = *(unsigned*)&Al[r + 8][kb];
                al[2] = *(unsigned*)&Al[r][kb + 8];
                al[3] = *(unsigned*)&Al[r + 8][kb + 8];
#pragma unroll
                for (int nf = 0; nf < 4; nf++) {
                    mma16816(acc[mf][nf], ah, bh[nf]);
                    mma16816(acc[mf][nf], ah, bl[nf]);
                    mma16816(acc[mf][nf], al, bh[nf]);
                }
            }
        }
    }

#pragma unroll
    for (int mf = 0; mf < 4; mf++) {
        int r = row0 + wm * 64 + mf * 16 + g;
#pragma unroll
        for (int nf = 0; nf < 4; nf++) {
            int c = col0 + wn * 32 + nf * 8 + tg * 2;
            *(float2*)&C[(size_t)r * N + c]       = make_float2(acc[mf][nf][0], acc[mf][nf][1]);
            *(float2*)&C[(size_t)(r + 8) * N + c] = make_float2(acc[mf][nf][2], acc[mf][nf][3]);
        }
    }
}

// ============================================================================
// Tensor-core fused rel-attention (flash-style, bf16-split MMAs).
// Grid (QLEN/64, NH, BSZ), 256 threads (8 warps).
// S[i,j] = (q_i+rwb)·k_j + (q_i+rrb)·r_k[1023-i+j], causal mask, softmax, ·V.
// BD via G = Qr @ band^T (two 64-col halves), BD[r][c] = G[r][63-r+c].
// ============================================================================
#define ROWP 72
#define TBYTES (64*ROWP*2)        /* 9216 bytes per bf16 tile */
#define OFF_UNION (10*TBYTES)     /* 92160: G (f32 64x133) aliases P hi/lo  */
#define GSTR 133
#define OFF_MISC (OFF_UNION + 64*GSTR*4)   /* 92160+34048 = 126208 */
#define ATTN_SMEM (OFF_MISC + 3*256 + 2*512)  /* 128000 */

__global__ __launch_bounds__(256) void attn_mma(
    const float* __restrict__ heads, const float* __restrict__ rk,
    const float* __restrict__ rwb, const float* __restrict__ rrb,
    float* __restrict__ vec)
{
    extern __shared__ char smc[];
    __nv_bfloat16* qw_h = (__nv_bfloat16*)(smc);
    __nv_bfloat16* qw_l = (__nv_bfloat16*)(smc + 1*TBYTES);
    __nv_bfloat16* qr_h = (__nv_bfloat16*)(smc + 2*TBYTES);
    __nv_bfloat16* qr_l = (__nv_bfloat16*)(smc + 3*TBYTES);
    __nv_bfloat16* kk_h = (__nv_bfloat16*)(smc + 4*TBYTES);
    __nv_bfloat16* kk_l = (__nv_bfloat16*)(smc + 5*TBYTES);
    __nv_bfloat16* vt_h = (__nv_bfloat16*)(smc + 6*TBYTES);   // [d][j]
    __nv_bfloat16* vt_l = (__nv_bfloat16*)(smc + 7*TBYTES);
    __nv_bfloat16* bd_h = (__nv_bfloat16*)(smc + 8*TBYTES);   // band half [t][d]
    __nv_bfloat16* bd_l = (__nv_bfloat16*)(smc + 9*TBYTES);
    __nv_bfloat16* pp_h = (__nv_bfloat16*)(smc + OFF_UNION);            // [r][j]
    __nv_bfloat16* pp_l = (__nv_bfloat16*)(smc + OFF_UNION + TBYTES);
    float* G      = (float*)(smc + OFF_UNION);   // aliases pp (disjoint in time)
    float* m_s    = (float*)(smc + OFF_MISC);
    float* l_s    = (float*)(smc + OFF_MISC + 256);
    float* corr_s = (float*)(smc + OFF_MISC + 512);
    float* pmax   = (float*)(smc + OFF_MISC + 768);    // [2][64]
    float* psum   = (float*)(smc + OFF_MISC + 1280);   // [2][64]

    const int tid = threadIdx.x;
    const int warp = tid >> 5, lane = tid & 31;
    const int g = lane >> 2, tg = lane & 3;
    const int mrow = (warp & 3) * 16;     // S rows [mrow, mrow+16)
    const int ncol = (warp >> 2) * 32;    // S col half
    const int wn = warp >> 2;
    const int i0 = blockIdx.x * 64;
    const int n  = blockIdx.y;
    const int b  = blockIdx.z;
    const int r0 = mrow + g, r1 = r0 + 8;

    // ---- Q load + biases, hi/lo split
    for (int idx = tid; idx < 4096; idx += 256) {
        int r = idx >> 6, d = idx & 63;
        float v = heads[(size_t)((i0 + r) * BSZ + b) * 3072 + n * 64 + d];
        float vw = v + rwb[n * 64 + d];
        float vr = v + rrb[n * 64 + d];
        __nv_bfloat16 h = __float2bfloat16(vw);
        qw_h[r * ROWP + d] = h;
        qw_l[r * ROWP + d] = __float2bfloat16(vw - __bfloat162float(h));
        h = __float2bfloat16(vr);
        qr_h[r * ROWP + d] = h;
        qr_l[r * ROWP + d] = __float2bfloat16(vr - __bfloat162float(h));
    }
    if (tid < 64) { m_s[tid] = -3.0e38f; l_s[tid] = 0.f; }

    float acc[4][4];
#pragma unroll
    for (int nf = 0; nf < 4; nf++)
#pragma unroll
        for (int i = 0; i < 4; i++) acc[nf][i] = 0.f;

    const float scale = 0.125f;
    const int ntiles = blockIdx.x + 1;

    for (int jt = 0; jt < ntiles; ++jt) {
        const int j0 = jt * 64;
        const int base = 960 - i0 + j0;
        __syncthreads();   // previous iter's P/V/K/band use complete

        // ---- load K tile + V^T tile (split)
        for (int idx = tid; idx < 4096; idx += 256) {
            int c = idx >> 6, d = idx & 63;
            size_t off = (size_t)((j0 + c) * BSZ + b) * 3072 + n * 64 + d;
            float kv = heads[off + 1024];
            float vv = heads[off + 2048];
            __nv_bfloat16 h = __float2bfloat16(kv);
            kk_h[c * ROWP + d] = h;
            kk_l[c * ROWP + d] = __float2bfloat16(kv - __bfloat162float(h));
            h = __float2bfloat16(vv);
            vt_h[d * ROWP + c] = h;
            vt_l[d * ROWP + c] = __float2bfloat16(vv - __bfloat162float(h));
        }
        // ---- band half 0 (t=0..63; base+t always within [0,1023])
        for (int idx = tid; idx < 4096; idx += 256) {
            int t = idx >> 6, d = idx & 63;
            float bv = rk[(size_t)(base + t) * HD + n * 64 + d];
            __nv_bfloat16 h = __float2bfloat16(bv);
            bd_h[t * ROWP + d] = h;
            bd_l[t * ROWP + d] = __float2bfloat16(bv - __bfloat162float(h));
        }
        __syncthreads();

        // ---- MMA: G half 0 = Qr @ band0^T
        {
            float gacc[4][4];
#pragma unroll
            for (int nf = 0; nf < 4; nf++)
#pragma unroll
                for (int i = 0; i < 4; i++) gacc[nf][i] = 0.f;
#pragma unroll
            for (int ks = 0; ks < 4; ks++) {
                int kb = ks * 16 + tg * 2;
                unsigned ah[4], al[4];
                ah[0] = *(unsigned*)&qr_h[r0 * ROWP + kb];
                ah[1] = *(unsigned*)&qr_h[r1 * ROWP + kb];
                ah[2] = *(unsigned*)&qr_h[r0 * ROWP + kb + 8];
                ah[3] = *(unsigned*)&qr_h[r1 * ROWP + kb + 8];
                al[0] = *(unsigned*)&qr_l[r0 * ROWP + kb];
                al[1] = *(unsigned*)&qr_l[r1 * ROWP + kb];
                al[2] = *(unsigned*)&qr_l[r0 * ROWP + kb + 8];
                al[3] = *(unsigned*)&qr_l[r1 * ROWP + kb + 8];
#pragma unroll
                for (int nf = 0; nf < 4; nf++) {
                    int nn = ncol + nf * 8 + g;
                    unsigned bh[2], bl[2];
                    bh[0] = *(unsigned*)&bd_h[nn * ROWP + kb];
                    bh[1] = *(unsigned*)&bd_h[nn * ROWP + kb + 8];
                    bl[0] = *(unsigned*)&bd_l[nn * ROWP + kb];
                    bl[1] = *(unsigned*)&bd_l[nn * ROWP + kb + 8];
                    mma16816(gacc[nf], ah, bh);
                    mma16816(gacc[nf], ah, bl);
                    mma16816(gacc[nf], al, bh);
                }
            }
#pragma unroll
            for (int nf = 0; nf < 4; nf++) {
                int col = ncol + nf * 8 + tg * 2;
                G[r0 * GSTR + col]     = gacc[nf][0];
                G[r0 * GSTR + col + 1] = gacc[nf][1];
                G[r1 * GSTR + col]     = gacc[nf][2];
                G[r1 * GSTR + col + 1] = gacc[nf][3];
            }
        }
        __syncthreads();   // band0 reads done; G half0 visible

        // ---- band half 1 load (base+64+t; mask rows past QLEN)
        for (int idx = tid; idx < 4096; idx += 256) {
            int t = idx >> 6, d = idx & 63;
            int grow = base + 64 + t;
            float bv = (grow < QLEN) ? rk[(size_t)grow * HD + n * 64 + d] : 0.f;
            __nv_bfloat16 h = __float2bfloat16(bv);
            bd_h[t * ROWP + d] = h;
            bd_l[t * ROWP + d] = __float2bfloat16(bv - __bfloat162float(h));
        }
        // ---- MMA: AC = Qw @ K^T (independent of band buffer)
        float sacc[4][4];
#pragma unroll
        for (int nf = 0; nf < 4; nf++)
#pragma unroll
            for (int i = 0; i < 4; i++) sacc[nf][i] = 0.f;
#pragma unroll
        for (int ks = 0; ks < 4; ks++) {
            int kb = ks * 16 + tg * 2;
            unsigned ah[4], al[4];
            ah[0] = *(unsigned*)&qw_h[r0 * ROWP + kb];
            ah[1] = *(unsigned*)&qw_h[r1 * ROWP + kb];
            ah[2] = *(unsigned*)&qw_h[r0 * ROWP + kb + 8];
            ah[3] = *(unsigned*)&qw_h[r1 * ROWP + kb + 8];
            al[0] = *(unsigned*)&qw_l[r0 * ROWP + kb];
            al[1] = *(unsigned*)&qw_l[r1 * ROWP + kb];
            al[2] = *(unsigned*)&qw_l[r0 * ROWP + kb + 8];
            al[3] = *(unsigned*)&qw_l[r1 * ROWP + kb + 8];
#pragma unroll
            for (int nf = 0; nf < 4; nf++) {
                int nn = ncol + nf * 8 + g;
                unsigned bh[2], bl[2];
                bh[0] = *(unsigned*)&kk_h[nn * ROWP + kb];
                bh[1] = *(unsigned*)&kk_h[nn * ROWP + kb + 8];
                bl[0] = *(unsigned*)&kk_l[nn * ROWP + kb];
                bl[1] = *(unsigned*)&kk_l[nn * ROWP + kb + 8];
                mma16816(sacc[nf], ah, bh);
                mma16816(sacc[nf], ah, bl);
                mma16816(sacc[nf], al, bh);
            }
        }
        __syncthreads();   // band1 ready

        // ---- MMA: G half 1 = Qr @ band1^T
        {
            float gacc[4][4];
#pragma unroll
            for (int nf = 0; nf < 4; nf++)
#pragma unroll
                for (int i = 0; i < 4; i++) gacc[nf][i] = 0.f;
#pragma unroll
            for (int ks = 0; ks < 4; ks++) {
                int kb = ks * 16 + tg * 2;
                unsigned ah[4], al[4];
                ah[0] = *(unsigned*)&qr_h[r0 * ROWP + kb];
                ah[1] = *(unsigned*)&qr_h[r1 * ROWP + kb];
                ah[2] = *(unsigned*)&qr_h[r0 * ROWP + kb + 8];
                ah[3] = *(unsigned*)&qr_h[r1 * ROWP + kb + 8];
                al[0] = *(unsigned*)&qr_l[r0 * ROWP + kb];
                al[1] = *(unsigned*)&qr_l[r1 * ROWP + kb];
                al[2] = *(unsigned*)&qr_l[r0 * ROWP + kb + 8];
                al[3] = *(unsigned*)&qr_l[r1 * ROWP + kb + 8];
#pragma unroll
                for (int nf = 0; nf < 4; nf++) {
                    int nn = ncol + nf * 8 + g;
                    unsigned bh[2], bl[2];
                    bh[0] = *(unsigned*)&bd_h[nn * ROWP + kb];
                    bh[1] = *(unsigned*)&bd_h[nn * ROWP + kb + 8];
                    bl[0] = *(unsigned*)&bd_l[nn * ROWP + kb];
                    bl[1] = *(unsigned*)&bd_l[nn * ROWP + kb + 8];
                    mma16816(gacc[nf], ah, bh);
                    mma16816(gacc[nf], ah, bl);
                    mma16816(gacc[nf], al, bh);
                }
            }
#pragma unroll
            for (int nf = 0; nf < 4; nf++) {
                int col = 64 + ncol + nf * 8 + tg * 2;
                G[r0 * GSTR + col]     = gacc[nf][0];
                G[r0 * GSTR + col + 1] = gacc[nf][1];
                G[r1 * GSTR + col]     = gacc[nf][2];
                G[r1 * GSTR + col + 1] = gacc[nf][3];
            }
        }
        __syncthreads();   // G complete

        // ---- epilogue: s = (AC + G[r][63-r+c])*scale, causal mask, row max
        float rmax0 = -3.0e38f, rmax1 = -3.0e38f;
#pragma unroll
        for (int nf = 0; nf < 4; nf++) {
            int col = ncol + nf * 8 + tg * 2;
            float s00 = (sacc[nf][0] + G[r0 * GSTR + 63 - r0 + col])     * scale;
            float s01 = (sacc[nf][1] + G[r0 * GSTR + 63 - r0 + col + 1]) * scale;
            float s10 = (sacc[nf][2] + G[r1 * GSTR + 63 - r1 + col])     * scale;
            float s11 = (sacc[nf][3] + G[r1 * GSTR + 63 - r1 + col + 1]) * scale;
            int ir0 = i0 + r0, ir1 = i0 + r1;
            int jc = j0 + col;
            s00 = (jc     <= ir0) ? s00 : -1.0e30f;
            s01 = (jc + 1 <= ir0) ? s01 : -1.0e30f;
            s10 = (jc     <= ir1) ? s10 : -1.0e30f;
            s11 = (jc + 1 <= ir1) ? s11 : -1.0e30f;
            sacc[nf][0] = s00; sacc[nf][1] = s01;
            sacc[nf][2] = s10; sacc[nf][3] = s11;
            rmax0 = fmaxf(rmax0, fmaxf(s00, s01));
            rmax1 = fmaxf(rmax1, fmaxf(s10, s11));
        }
        rmax0 = fmaxf(rmax0, __shfl_xor_sync(0xffffffffu, rmax0, 1));
        rmax0 = fmaxf(rmax0, __shfl_xor_sync(0xffffffffu, rmax0, 2));
        rmax1 = fmaxf(rmax1, __shfl_xor_sync(0xffffffffu, rmax1, 1));
        rmax1 = fmaxf(rmax1, __shfl_xor_sync(0xffffffffu, rmax1, 2));
        if (tg == 0) { pmax[wn * 64 + r0] = rmax0; pmax[wn * 64 + r1] = rmax1; }
        __syncthreads();

        // ---- exp + P write (aliases G; all G reads done above)
        float nm0 = fmaxf(m_s[r0], fmaxf(pmax[r0], pmax[64 + r0]));
        float nm1 = fmaxf(m_s[r1], fmaxf(pmax[r1], pmax[64 + r1]));
        float rs0 = 0.f, rs1 = 0.f;
#pragma unroll
        for (int nf = 0; nf < 4; nf++) {
            int col = ncol + nf * 8 + tg * 2;
            float p00 = __expf(sacc[nf][0] - nm0);
            float p01 = __expf(sacc[nf][1] - nm0);
            float p10 = __expf(sacc[nf][2] - nm1);
            float p11 = __expf(sacc[nf][3] - nm1);
            rs0 += p00 + p01; rs1 += p10 + p11;
            __nv_bfloat16 h00 = __float2bfloat16(p00);
            __nv_bfloat16 h01 = __float2bfloat16(p01);
            __nv_bfloat16 h10 = __float2bfloat16(p10);
            __nv_bfloat16 h11 = __float2bfloat16(p11);
            *(unsigned*)&pp_h[r0 * ROWP + col] = pack_bf2(h00, h01);
            *(unsigned*)&pp_h[r1 * ROWP + col] = pack_bf2(h10, h11);
            *(unsigned*)&pp_l[r0 * ROWP + col] = pack_bf2(
                __float2bfloat16(p00 - __bfloat162float(h00)),
                __float2bfloat16(p01 - __bfloat162float(h01)));
            *(unsigned*)&pp_l[r1 * ROWP + col] = pack_bf2(
                __float2bfloat16(p10 - __bfloat162float(h10)),
                __float2bfloat16(p11 - __bfloat162float(h11)));
        }
        rs0 += __shfl_xor_sync(0xffffffffu, rs0, 1);
        rs0 += __shfl_xor_sync(0xffffffffu, rs0, 2);
        rs1 += __shfl_xor_sync(0xffffffffu, rs1, 1);
        rs1 += __shfl_xor_sync(0xffffffffu, rs1, 2);
        if (tg == 0) { psum[wn * 64 + r0] = rs0; psum[wn * 64 + r1] = rs1; }
        __syncthreads();

        // ---- flash state update (one thread per row)
        if (tid < 64) {
            float mo = m_s[tid];
            float nm = fmaxf(mo, fmaxf(pmax[tid], pmax[64 + tid]));
            float co = __expf(mo - nm);
            corr_s[tid] = co;
            l_s[tid] = l_s[tid] * co + psum[tid] + psum[64 + tid];
            m_s[tid] = nm;
        }
        __syncthreads();

        // ---- PV: acc = acc*corr + P @ V^T
        float c0 = corr_s[r0], c1 = corr_s[r1];
#pragma unroll
        for (int nf = 0; nf < 4; nf++) {
            acc[nf][0] *= c0; acc[nf][1] *= c0;
            acc[nf][2] *= c1; acc[nf][3] *= c1;
        }
#pragma unroll
        for (int ks = 0; ks < 4; ks++) {
            int kb = ks * 16 + tg * 2;
            unsigned ah[4], al[4];
            ah[0] = *(unsigned*)&pp_h[r0 * ROWP + kb];
            ah[1] = *(unsigned*)&pp_h[r1 * ROWP + kb];
            ah[2] = *(unsigned*)&pp_h[r0 * ROWP + kb + 8];
            ah[3] = *(unsigned*)&pp_h[r1 * ROWP + kb + 8];
            al[0] = *(unsigned*)&pp_l[r0 * ROWP + kb];
            al[1] = *(unsigned*)&pp_l[r1 * ROWP + kb];
            al[2] = *(unsigned*)&pp_l[r0 * ROWP + kb + 8];
            al[3] = *(unsigned*)&pp_l[r1 * ROWP + kb + 8];
#pragma unroll
            for (int nf = 0; nf < 4; nf++) {
                int nn = ncol + nf * 8 + g;
                unsigned bh[2], bl[2];
                bh[0] = *(unsigned*)&vt_h[nn * ROWP + kb];
                bh[1] = *(unsigned*)&vt_h[nn * ROWP + kb + 8];
                bl[0] = *(unsigned*)&vt_l[nn * ROWP + kb];
                bl[1] = *(unsigned*)&vt_l[nn * ROWP + kb + 8];
                mma16816(acc[nf], ah, bh);
                mma16816(acc[nf], ah, bl);
                mma16816(acc[nf], al, bh);
            }
        }
    }

    // ---- output: vec = acc / l
    float inv0 = 1.0f / l_s[r0];
    float inv1 = 1.0f / l_s[r1];
#pragma unroll
    for (int nf = 0; nf < 4; nf++) {
        int col = ncol + nf * 8 + tg * 2;
        size_t o0 = (size_t)((i0 + r0) * BSZ + b) * HD + n * 64 + col;
        size_t o1 = (size_t)((i0 + r1) * BSZ + b) * HD + n * 64 + col;
        *(float2*)&vec[o0] = make_float2(acc[nf][0] * inv0, acc[nf][1] * inv0);
        *(float2*)&vec[o1] = make_float2(acc[nf][2] * inv1, acc[nf][3] * inv1);
    }
}

// ---------------- residual + LayerNorm -------------------------------------
__global__ __launch_bounds__(256) void ln_kernel(
    const float* __restrict__ w, const float* __restrict__ ao,
    const float* __restrict__ gamma, const float* __restrict__ beta,
    float* __restrict__ out)
{
    int row = blockIdx.x;
    const float* wr = w  + (size_t)row * DM;
    const float* ar = ao + (size_t)row * DM;
    int tid = threadIdx.x;

    float x[4];
    float sum = 0.f, ssq = 0.f;
#pragma unroll
    for (int k = 0; k < 4; k++) {
        int d = tid + k * 256;
        x[k] = wr[d] + ar[d];
        sum += x[k];
        ssq += x[k] * x[k];
    }
#pragma unroll
    for (int o = 16; o > 0; o >>= 1) {
        sum += __shfl_xor_sync(0xffffffffu, sum, o);
        ssq += __shfl_xor_sync(0xffffffffu, ssq, o);
    }
    __shared__ float reds[8], redq[8];
    __shared__ float mu_s, rstd_s;
    int wid = tid >> 5, lane = tid & 31;
    if (lane == 0) { reds[wid] = sum; redq[wid] = ssq; }
    __syncthreads();
    if (tid == 0) {
        float s = 0.f, q = 0.f;
#pragma unroll
        for (int i = 0; i < 8; i++) { s += reds[i]; q += redq[i]; }
        float mu = s * (1.0f / DM);
        float var = q * (1.0f / DM) - mu * mu;
        mu_s = mu;
        rstd_s = rsqrtf(var + 1e-5f);
    }
    __syncthreads();
    float mu = mu_s, rstd = rstd_s;
#pragma unroll
    for (int k = 0; k < 4; k++) {
        int d = tid + k * 256;
        out[(size_t)row * DM + d] = (x[k] - mu) * rstd * gamma[d] + beta[d];
    }
}

// ---------------- launch ----------------------------------------------------
extern "C" void kernel_launch(void* const* d_in, const int* in_sizes, int n_in,
                              void* d_out, int out_size)
{
    const float* w    = (const float*)d_in[0];
    const float* r    = (const float*)d_in[1];
    const float* rwb  = (const float*)d_in[2];
    const float* rrb  = (const float*)d_in[3];
    // d_in[4] = attn_mask: deterministic causal tril -> applied analytically
    const float* Wqkv = (const float*)d_in[5];
    const float* Wr   = (const float*)d_in[6];
    const float* Wo   = (const float*)d_in[7];
    const float* gam  = (const float*)d_in[8];
    const float* bet  = (const float*)d_in[9];
    float* out = (float*)d_out;

    float *heads, *rkp, *vecp, *aop;
    cudaGetSymbolAddress((void**)&heads, g_heads);
    cudaGetSymbolAddress((void**)&rkp,   g_rk);
    cudaGetSymbolAddress((void**)&vecp,  g_vec);
    cudaGetSymbolAddress((void**)&aop,   g_ao);

    // 1) heads = w @ W_qkv   [4096,1024]x[1024,3072]
    gemm_mma<<<dim3(3072 / 128, 4096 / 128), 256>>>(w, Wqkv, heads, ROWS, 3 * HD, DM);
    // 2) r_k = r @ W_r       [1024,1024]x[1024,1024]
    gemm_mma<<<dim3(HD / 128, QLEN / 128), 256>>>(r, Wr, rkp, QLEN, HD, DM);

    // 3) fused relative attention (tensor cores)
    cudaFuncSetAttribute(attn_mma, cudaFuncAttributeMaxDynamicSharedMemorySize,
                         ATTN_SMEM);
    attn_mma<<<dim3(QLEN / 64, NH, BSZ), 256, ATTN_SMEM>>>(heads, rkp, rwb, rrb, vecp);

    // 4) attn_out = vec @ W_o
    gemm_mma<<<dim3(DM / 128, ROWS / 128), 256>>>(vecp, Wo, aop, ROWS, DM, HD);

    // 5) residual + layernorm
    ln_kernel<<<ROWS, 256>>>(w, aop, gam, bet, out);
}